// round 4
// baseline (speedup 1.0000x reference)
#include <cuda_runtime.h>
#include <cuda_bf16.h>

#define DIM 128
#define NVOX (DIM * DIM * DIM)

__global__ void __launch_bounds__(256) cafe_rnn_kernel(
    const float* __restrict__ x,     // [NVOX, 5]: state0, euler0(3), field0
    const float* __restrict__ out,   // [NVOX, 8]: logits(4), rot1(3), field(1)
    float* __restrict__ y)           // [NVOX, 5]: state1, euler1(3), field1
{
    int idx = blockIdx.x * blockDim.x + threadIdx.x;
    if (idx >= NVOX) return;

    int k = idx & (DIM - 1);
    int j = (idx >> 7) & (DIM - 1);
    int i = idx >> 14;

    const float* xp = x + (size_t)idx * 5;
    float s0f = __ldg(xp + 0);
    float e0x = __ldg(xp + 1), e0y = __ldg(xp + 2), e0z = __ldg(xp + 3);
    int state0 = (int)s0f;

    const float4* op = reinterpret_cast<const float4*>(out + (size_t)idx * 8);
    float4 o0 = __ldg(op + 0);   // logits
    float4 o1 = __ldg(op + 1);   // rot1(3), field

    // argmax over 4 logits, first-occurrence on ties (strict >)
    int amax = 0;
    float mv = o0.x;
    if (o0.y > mv) { mv = o0.y; amax = 1; }
    if (o0.z > mv) { mv = o0.z; amax = 2; }
    if (o0.w > mv) { mv = o0.w; amax = 3; }

    int state1 = (state0 == 0) ? 0 : amax;

    // field1 masking
    float field1 = o1.w;
    if (state1 <= 1) {
        field1 = -1.0f;
    } else if (state1 == 2) {
        field1 = fminf(fmaxf(field1, 0.0f), 0.92f);
    } else {  // state1 == 3
        field1 = 1.0f;
    }

    // euler1 default
    float ex = e0x, ey = e0y, ez = e0z;
    if (state1 <= 1) { ex = -1.0f; ey = -1.0f; ez = -1.0f; }

    // solidify: pick nearest neighbor euler to rot1 (26-neighborhood, zero-padded,
    // first-occurrence argmin via strict <)
    if (state0 <= 1 && state1 > 1) {
        float rx = o1.x, ry = o1.y, rz = o1.z;
        float best = 3.402823e38f;
        float cx = 0.0f, cy = 0.0f, cz = 0.0f;
        #pragma unroll
        for (int di = -1; di <= 1; di++) {
            #pragma unroll
            for (int dj = -1; dj <= 1; dj++) {
                #pragma unroll
                for (int dk = -1; dk <= 1; dk++) {
                    if (di == 0 && dj == 0 && dk == 0) continue;
                    int ni = i + di, nj = j + dj, nk = k + dk;
                    float nx = 0.0f, ny = 0.0f, nz = 0.0f;
                    if ((unsigned)ni < DIM && (unsigned)nj < DIM && (unsigned)nk < DIM) {
                        const float* np =
                            x + (size_t)((ni << 14) | (nj << 7) | nk) * 5;
                        nx = __ldg(np + 1); ny = __ldg(np + 2); nz = __ldg(np + 3);
                    }
                    float dx = nx - rx, dy = ny - ry, dz = nz - rz;
                    float d2 = dx * dx + dy * dy + dz * dz;
                    if (d2 < best) { best = d2; cx = nx; cy = ny; cz = nz; }
                }
            }
        }
        ex = cx; ey = cy; ez = cz;
    }

    float* yp = y + (size_t)idx * 5;
    yp[0] = (float)state1;
    yp[1] = ex;
    yp[2] = ey;
    yp[3] = ez;
    yp[4] = field1;
}

extern "C" void kernel_launch(void* const* d_in, const int* in_sizes, int n_in,
                              void* d_out, int out_size)
{
    const float* x   = (const float*)d_in[0];   // NVOX*5 elements
    const float* out = (const float*)d_in[1];   // NVOX*8 elements
    float* y = (float*)d_out;                   // NVOX*5 elements

    const int threads = 256;
    const int blocks = (NVOX + threads - 1) / threads;
    cafe_rnn_kernel<<<blocks, threads>>>(x, out, y);
}